// round 6
// baseline (speedup 1.0000x reference)
#include <cuda_runtime.h>

// ---------------------------------------------------------------------------
// DecoderBlock: x:(8,2048,32), H=4, hd=8. fp32, f32x2 packed FMA.
// Attention: causal-balanced pairing at 32-query granularity —
// block (bh, jj) handles query tiles jj and 63-jj (uniform ~17 key-tile
// visits), 1024 blocks for 98.8% SM utilization, one warp per key parity.
// ---------------------------------------------------------------------------

constexpr int B_  = 8;
constexpr int T_  = 2048;
constexpr int D_  = 32;
constexpr int BT_ = B_ * T_;

__device__ float g_h[BT_ * D_];   // LN1 output
__device__ float g_q[BT_ * D_];   // (B,H,T,8), pre-scaled by log2e/sqrt(8)
__device__ float g_k[BT_ * D_];
__device__ float g_v[BT_ * D_];
__device__ float g_o[BT_ * D_];   // attention out (B*T,32), normalized

typedef unsigned long long u64;

static __device__ __forceinline__ u64 ffma2(u64 a, u64 b, u64 c) {
    u64 d; asm("fma.rn.f32x2 %0, %1, %2, %3;" : "=l"(d) : "l"(a), "l"(b), "l"(c));
    return d;
}
static __device__ __forceinline__ u64 fmul2(u64 a, u64 b) {
    u64 d; asm("mul.rn.f32x2 %0, %1, %2;" : "=l"(d) : "l"(a), "l"(b));
    return d;
}
static __device__ __forceinline__ u64 fadd2(u64 a, u64 b) {
    u64 d; asm("add.rn.f32x2 %0, %1, %2;" : "=l"(d) : "l"(a), "l"(b));
    return d;
}
static __device__ __forceinline__ u64 pack2(float x, float y) {
    u64 d; asm("mov.b64 %0, {%1, %2};" : "=l"(d) : "f"(x), "f"(y));
    return d;
}
static __device__ __forceinline__ float2 unpack2(u64 d) {
    float2 r; asm("mov.b64 {%0, %1}, %2;" : "=f"(r.x), "=f"(r.y) : "l"(d));
    return r;
}
static __device__ __forceinline__ float ex2f(float x) {
    float r; asm("ex2.approx.ftz.f32 %0, %1;" : "=f"(r) : "f"(x));
    return r;
}

// ---------------------------------------------------------------------------
// Kernel 1: LN1 + QKV. 16 tokens/block, 128 threads, grid 1024.
// ---------------------------------------------------------------------------
__global__ __launch_bounds__(128) void k_ln_qkv(
    const float* __restrict__ x,
    const float* __restrict__ Wq, const float* __restrict__ Wk,
    const float* __restrict__ Wv,
    const float* __restrict__ g1, const float* __restrict__ b1)
{
    __shared__ __align__(16) float sh_h[16][33];
    __shared__ __align__(16) float sh_w[32][96];   // [d][qkv*32 + head*8 + kk]

    const int tid = threadIdx.x;
    const int t0  = blockIdx.x * 16;

    for (int i = tid; i < 3072; i += 128) {
        int type = i >> 10, rem = i & 1023;
        int head = rem >> 8, d = (rem >> 3) & 31, kk = rem & 7;
        const float* W = (type == 0) ? Wq : (type == 1) ? Wk : Wv;
        sh_w[d][type * 32 + head * 8 + kk] = W[(head * 32 + d) * 8 + kk];
    }

    // LN: 8 lanes per token, 4 values each
    const int tk = tid >> 3, part = tid & 7;
    const int t  = t0 + tk;
    const int c0 = part * 4;
    float4 v0 = *(const float4*)(x + t * 32 + c0);
    float s  = v0.x + v0.y + v0.z + v0.w;
    float ss = v0.x*v0.x + v0.y*v0.y + v0.z*v0.z + v0.w*v0.w;
    s  += __shfl_xor_sync(0xffffffffu, s, 1);
    ss += __shfl_xor_sync(0xffffffffu, ss, 1);
    s  += __shfl_xor_sync(0xffffffffu, s, 2);
    ss += __shfl_xor_sync(0xffffffffu, ss, 2);
    s  += __shfl_xor_sync(0xffffffffu, s, 4);
    ss += __shfl_xor_sync(0xffffffffu, ss, 4);
    const float mu = s * 0.03125f;
    const float rs = rsqrtf(ss * 0.03125f - mu * mu + 1e-5f);
    float hv[4];
    {
        const float* vv = (const float*)&v0;
        #pragma unroll
        for (int i = 0; i < 4; i++)
            hv[i] = (vv[i] - mu) * rs * __ldg(g1 + c0 + i) + __ldg(b1 + c0 + i);
    }
    #pragma unroll
    for (int i = 0; i < 4; i++) sh_h[tk][c0 + i] = hv[i];
    *(float4*)(g_h + t * 32 + c0) = make_float4(hv[0], hv[1], hv[2], hv[3]);
    __syncthreads();

    // GEMM: thread = 1 token x 12 outs
    const int to = tid >> 3;   // 0..15
    const int oo = tid & 7;    // 0..7
    u64 acc[6] = {0,0,0,0,0,0};

    #pragma unroll 4
    for (int kd = 0; kd < 32; kd++) {
        float a = sh_h[to][kd];
        u64 ap = pack2(a, a);
        const ulonglong2* wr = (const ulonglong2*)&sh_w[kd][oo * 12];
        ulonglong2 w0 = wr[0], w1 = wr[1], w2 = wr[2];
        acc[0] = ffma2(ap, w0.x, acc[0]); acc[1] = ffma2(ap, w0.y, acc[1]);
        acc[2] = ffma2(ap, w1.x, acc[2]); acc[3] = ffma2(ap, w1.y, acc[3]);
        acc[4] = ffma2(ap, w2.x, acc[4]); acc[5] = ffma2(ap, w2.y, acc[5]);
    }

    const float QS = 0.51006973f;            // log2(e)/sqrt(8)
    const int b  = t0 >> 11;
    const int tt = (t0 & 2047) + to;
    #pragma unroll
    for (int i2 = 0; i2 < 6; i2++) {
        int o    = oo * 12 + 2 * i2;
        int type = o >> 5;
        int head = (o >> 3) & 3;
        int kk   = o & 7;
        float* base = (type == 0) ? g_q : (type == 1) ? g_k : g_v;
        float sc = (type == 0) ? QS : 1.f;
        float2 u = unpack2(acc[i2]);
        *(float2*)(base + ((b * 4 + head) * 2048 + tt) * 8 + kk)
            = make_float2(u.x * sc, u.y * sc);
    }
}

// ---------------------------------------------------------------------------
// Kernel 2: causal attention, balanced pairing, fine granularity.
// grid (32, 32), 64 threads. Block (bh, jj): 32-query tiles jj and 63-jj.
// warp = key-tile parity; per-warp partials merged via smem at end.
// ---------------------------------------------------------------------------
static __device__ __forceinline__ void attn_pair(
    const u64* __restrict__ q, const ulonglong2& kA, const ulonglong2& kB,
    const ulonglong2& kC, const ulonglong2& kD,
    const ulonglong2& va0, const ulonglong2& va1,
    const ulonglong2& vb0, const ulonglong2& vb1,
    u64* __restrict__ o, float& l, bool m0, bool m1)
{
    u64 e = fmul2(q[0], kA.x); e = ffma2(q[2], kB.x, e);
    e = ffma2(q[4], kC.x, e);  e = ffma2(q[6], kD.x, e);
    u64 od = fmul2(q[1], kA.y); od = ffma2(q[3], kB.y, od);
    od = ffma2(q[5], kC.y, od); od = ffma2(q[7], kD.y, od);
    float2 d = unpack2(fadd2(e, od));
    float p0 = m0 ? ex2f(d.x) : 0.f;
    float p1 = m1 ? ex2f(d.y) : 0.f;
    l += p0 + p1;
    u64 pp0 = pack2(p0, p0), pp1 = pack2(p1, p1);
    o[0] = ffma2(pp0, va0.x, o[0]); o[1] = ffma2(pp0, va0.y, o[1]);
    o[2] = ffma2(pp0, va1.x, o[2]); o[3] = ffma2(pp0, va1.y, o[3]);
    o[0] = ffma2(pp1, vb0.x, o[0]); o[1] = ffma2(pp1, vb0.y, o[1]);
    o[2] = ffma2(pp1, vb1.x, o[2]); o[3] = ffma2(pp1, vb1.y, o[3]);
}

__global__ __launch_bounds__(64) void k_attn()
{
    __shared__ __align__(16) u64    sKp[2][640];    // [half][keypair*10 + dim]
    __shared__ __align__(16) float4 sV [2][256];    // [half][key*2 + dimhalf]
    __shared__ float sPart[32 * 20];

    const int tid  = threadIdx.x;
    const int half = tid >> 5;         // warp = key-tile parity
    const int ht   = tid & 31;
    const int bh   = blockIdx.x;
    const int jj   = blockIdx.y;       // 0..31 -> query tiles jj and 63-jj
    const int tqa  = jj * 32 + ht;
    const int tqb  = (63 - jj) * 32 + ht;
    const int jaq  = jj >> 2;          // qa diagonal key tile
    const int jbq  = (63 - jj) >> 2;   // qb diagonal key tile (= loop bound)

    u64 qa[8], qq[8];
    {
        const float4* pa = (const float4*)(g_q + (bh * T_ + tqa) * 8);
        float4 a0 = pa[0], a1 = pa[1];
        qa[0]=pack2(a0.x,a0.x); qa[1]=pack2(a0.y,a0.y); qa[2]=pack2(a0.z,a0.z); qa[3]=pack2(a0.w,a0.w);
        qa[4]=pack2(a1.x,a1.x); qa[5]=pack2(a1.y,a1.y); qa[6]=pack2(a1.z,a1.z); qa[7]=pack2(a1.w,a1.w);
        const float4* pb = (const float4*)(g_q + (bh * T_ + tqb) * 8);
        float4 b0 = pb[0], b1 = pb[1];
        qq[0]=pack2(b0.x,b0.x); qq[1]=pack2(b0.y,b0.y); qq[2]=pack2(b0.z,b0.z); qq[3]=pack2(b0.w,b0.w);
        qq[4]=pack2(b1.x,b1.x); qq[5]=pack2(b1.y,b1.y); qq[6]=pack2(b1.z,b1.z); qq[7]=pack2(b1.w,b1.w);
    }

    u64 oa[4] = {0,0,0,0}, ob[4] = {0,0,0,0};
    float la = 0.f, lb = 0.f;

    const float4* vg = (const float4*)(g_v + bh * T_ * 8);

    for (int kt = half; kt <= jbq; kt += 2) {
        const int s0 = kt * 128;
        // stage K transposed+key-paired (2 pairs/thread) and V (8 vec4/thread)
        #pragma unroll
        for (int r = 0; r < 2; r++) {
            const int sp = ht + 32 * r;
            const float4* kg = (const float4*)(g_k + (bh * T_ + s0 + 2 * sp) * 8);
            float4 ka0 = kg[0], ka1 = kg[1];   // key 2sp
            float4 kb0 = kg[2], kb1 = kg[3];   // key 2sp+1
            u64* row = &sKp[half][sp * 10];
            row[0] = pack2(ka0.x, kb0.x); row[1] = pack2(ka0.y, kb0.y);
            row[2] = pack2(ka0.z, kb0.z); row[3] = pack2(ka0.w, kb0.w);
            row[4] = pack2(ka1.x, kb1.x); row[5] = pack2(ka1.y, kb1.y);
            row[6] = pack2(ka1.z, kb1.z); row[7] = pack2(ka1.w, kb1.w);
        }
        #pragma unroll
        for (int r = 0; r < 8; r++)
            sV[half][ht + 32 * r] = vg[s0 * 2 + ht + 32 * r];
        __syncwarp();

        if (kt < jaq) {
            // both queries, full
            #pragma unroll 2
            for (int sp = 0; sp < 64; sp++) {
                const ulonglong2* kr = (const ulonglong2*)&sKp[half][sp * 10];
                ulonglong2 kA = kr[0], kB = kr[1], kC = kr[2], kD = kr[3];
                const ulonglong2* vr = (const ulonglong2*)&sV[half][4 * sp];
                ulonglong2 va0 = vr[0], va1 = vr[1], vb0 = vr[2], vb1 = vr[3];
                attn_pair(qa, kA, kB, kC, kD, va0, va1, vb0, vb1, oa, la, true, true);
                attn_pair(qq, kA, kB, kC, kD, va0, va1, vb0, vb1, ob, lb, true, true);
            }
        } else if (kt == jaq) {
            // qa diagonal, qb full
            const int rel = tqa - s0;   // in [0,127]
            for (int sp = 0; sp < 64; sp++) {
                const ulonglong2* kr = (const ulonglong2*)&sKp[half][sp * 10];
                ulonglong2 kA = kr[0], kB = kr[1], kC = kr[2], kD = kr[3];
                const ulonglong2* vr = (const ulonglong2*)&sV[half][4 * sp];
                ulonglong2 va0 = vr[0], va1 = vr[1], vb0 = vr[2], vb1 = vr[3];
                attn_pair(qa, kA, kB, kC, kD, va0, va1, vb0, vb1, oa, la,
                          2 * sp <= rel, 2 * sp + 1 <= rel);
                attn_pair(qq, kA, kB, kC, kD, va0, va1, vb0, vb1, ob, lb, true, true);
            }
        } else if (kt < jbq) {
            // qb only, full
            #pragma unroll 2
            for (int sp = 0; sp < 64; sp++) {
                const ulonglong2* kr = (const ulonglong2*)&sKp[half][sp * 10];
                ulonglong2 kA = kr[0], kB = kr[1], kC = kr[2], kD = kr[3];
                const ulonglong2* vr = (const ulonglong2*)&sV[half][4 * sp];
                ulonglong2 va0 = vr[0], va1 = vr[1], vb0 = vr[2], vb1 = vr[3];
                attn_pair(qq, kA, kB, kC, kD, va0, va1, vb0, vb1, ob, lb, true, true);
            }
        } else {
            // qb diagonal
            const int rel = tqb - s0;   // in [0,127]
            for (int sp = 0; sp < 64; sp++) {
                const ulonglong2* kr = (const ulonglong2*)&sKp[half][sp * 10];
                ulonglong2 kA = kr[0], kB = kr[1], kC = kr[2], kD = kr[3];
                const ulonglong2* vr = (const ulonglong2*)&sV[half][4 * sp];
                ulonglong2 va0 = vr[0], va1 = vr[1], vb0 = vr[2], vb1 = vr[3];
                attn_pair(qq, kA, kB, kC, kD, va0, va1, vb0, vb1, ob, lb,
                          2 * sp <= rel, 2 * sp + 1 <= rel);
            }
        }
        __syncwarp();
    }

    if (half == 1) {
        float* pb = &sPart[ht * 20];
        #pragma unroll
        for (int i = 0; i < 4; i++) {
            float2 u = unpack2(oa[i]); pb[2*i] = u.x; pb[2*i+1] = u.y;
            float2 w = unpack2(ob[i]); pb[8+2*i] = w.x; pb[8+2*i+1] = w.y;
        }
        pb[16] = la; pb[17] = lb;
    }
    __syncthreads();
    if (half == 0) {
        const float* pb = &sPart[ht * 20];
        float oav[8], obv[8];
        #pragma unroll
        for (int i = 0; i < 4; i++) {
            float2 u = unpack2(oa[i]); oav[2*i] = u.x + pb[2*i]; oav[2*i+1] = u.y + pb[2*i+1];
            float2 w = unpack2(ob[i]); obv[2*i] = w.x + pb[8+2*i]; obv[2*i+1] = w.y + pb[8+2*i+1];
        }
        const float ra = __fdividef(1.f, la + pb[16]);
        const float rb = __fdividef(1.f, lb + pb[17]);
        const int b = bh >> 2, h = bh & 3;
        float4* opa = (float4*)(g_o + (b * T_ + tqa) * 32 + h * 8);
        opa[0] = make_float4(oav[0]*ra, oav[1]*ra, oav[2]*ra, oav[3]*ra);
        opa[1] = make_float4(oav[4]*ra, oav[5]*ra, oav[6]*ra, oav[7]*ra);
        float4* opb = (float4*)(g_o + (b * T_ + tqb) * 32 + h * 8);
        opb[0] = make_float4(obv[0]*rb, obv[1]*rb, obv[2]*rb, obv[3]*rb);
        opb[1] = make_float4(obv[4]*rb, obv[5]*rb, obv[6]*rb, obv[7]*rb);
    }
}

// ---------------------------------------------------------------------------
// Kernel 3: proj + residual + LN2 + FFN + residual. 32 tokens, 256 threads,
// grid 512.
// ---------------------------------------------------------------------------
constexpr int SM3_FLOATS = 1024 + 4096 + 4096 + 128 + 128 + 32 * 33 + 32 * 129;
constexpr int SM3_BYTES  = SM3_FLOATS * 4;   // ~57.3 KB

__global__ __launch_bounds__(256) void k_post(
    float* __restrict__ out,
    const float* __restrict__ Wp, const float* __restrict__ bp,
    const float* __restrict__ W1, const float* __restrict__ b1v,
    const float* __restrict__ W2, const float* __restrict__ b2v,
    const float* __restrict__ g2, const float* __restrict__ bt2)
{
    extern __shared__ float sm[];
    float* sWp  = sm;                 // [kd][32]
    float* sW1  = sWp + 1024;         // [k][128]
    float* sW2  = sW1 + 4096;         // [k][32]
    float* sB   = sW2 + 4096;         // 0:bproj 32:b2 64:ln2_g 96:ln2_b
    float* sb1  = sB + 128;
    float* sX   = sb1 + 128;          // 32 x 33
    float* sHid = sX + 32 * 33;       // 32 x 129

    const int tid = threadIdx.x;
    const int t0  = blockIdx.x * 32;

    for (int i = tid; i < 1024; i += 256) sWp[i] = Wp[i];
    for (int i = tid; i < 4096; i += 256) sW1[i] = W1[i];
    for (int i = tid; i < 4096; i += 256) sW2[i] = W2[i];
    if (tid < 32) { sB[tid] = bp[tid]; sB[32 + tid] = b2v[tid];
                    sB[64 + tid] = g2[tid]; sB[96 + tid] = bt2[tid]; }
    if (tid >= 128 && tid < 256) sb1[tid - 128] = b1v[tid - 128];

    {   // o tile -> sX  (32 tokens x 8 float4 = 256 = one per thread)
        int row = tid >> 3, c4 = tid & 7;
        float4 v = ((const float4*)(g_o + (t0 + row) * 32))[c4];
        float* d = &sX[row * 33 + c4 * 4];
        d[0] = v.x; d[1] = v.y; d[2] = v.z; d[3] = v.w;
    }
    __syncthreads();

    // ---- stage A: x1 = h + o@Wproj + bproj ; h2 = LN2(x1) ----
    const int tr = tid >> 3, q8 = tid & 7;   // token, col-eighth (4 cols)
    const int c0 = q8 * 4;
    const int gt = t0 + tr;
    u64 accp[2] = {0, 0};

    #pragma unroll 4
    for (int kd = 0; kd < 32; kd++) {
        float a = sX[tr * 33 + kd];
        u64 ap = pack2(a, a);
        ulonglong2 w0 = *(const ulonglong2*)&sWp[kd * 32 + c0];
        accp[0] = ffma2(ap, w0.x, accp[0]);
        accp[1] = ffma2(ap, w0.y, accp[1]);
    }
    float xv[4];
    {
        float4 h0 = *(const float4*)(g_h + gt * 32 + c0);
        float2 u0 = unpack2(accp[0]), u1 = unpack2(accp[1]);
        xv[0] = h0.x + u0.x + sB[c0 + 0];
        xv[1] = h0.y + u0.y + sB[c0 + 1];
        xv[2] = h0.z + u1.x + sB[c0 + 2];
        xv[3] = h0.w + u1.y + sB[c0 + 3];
    }
    float s = 0.f, ss = 0.f;
    #pragma unroll
    for (int i = 0; i < 4; i++) { s += xv[i]; ss += xv[i] * xv[i]; }
    s  += __shfl_xor_sync(0xffffffffu, s, 1);
    ss += __shfl_xor_sync(0xffffffffu, ss, 1);
    s  += __shfl_xor_sync(0xffffffffu, s, 2);
    ss += __shfl_xor_sync(0xffffffffu, ss, 2);
    s  += __shfl_xor_sync(0xffffffffu, s, 4);
    ss += __shfl_xor_sync(0xffffffffu, ss, 4);
    const float mu = s * 0.03125f;
    const float rs = rsqrtf(ss * 0.03125f - mu * mu + 1e-5f);
    float h2r[4];
    #pragma unroll
    for (int i = 0; i < 4; i++)
        h2r[i] = (xv[i] - mu) * rs * sB[64 + c0 + i] + sB[96 + c0 + i];

    __syncthreads();                 // all o-tile reads done; reuse sX for h2
    #pragma unroll
    for (int i = 0; i < 4; i++) sX[tr * 33 + c0 + i] = h2r[i];
    __syncthreads();

    // ---- stage B: hid = relu(h2 @ W1 + b1) ----
    const int ttb = tid >> 4;   // 0..15 -> 2 tokens each
    const int oo  = tid & 15;   // 8 outs each
    u64 accB[2][4];
    #pragma unroll
    for (int j = 0; j < 2; j++)
        #pragma unroll
        for (int i = 0; i < 4; i++) accB[j][i] = 0;

    #pragma unroll 4
    for (int k = 0; k < 32; k++) {
        float a0 = sX[(ttb * 2 + 0) * 33 + k];
        float a1 = sX[(ttb * 2 + 1) * 33 + k];
        u64 ap0 = pack2(a0, a0), ap1 = pack2(a1, a1);
        const ulonglong2* wr = (const ulonglong2*)&sW1[k * 128 + oo * 8];
        ulonglong2 ww0 = wr[0], ww1 = wr[1];
        u64 wv[4] = {ww0.x, ww0.y, ww1.x, ww1.y};
        #pragma unroll
        for (int i = 0; i < 4; i++) {
            accB[0][i] = ffma2(ap0, wv[i], accB[0][i]);
            accB[1][i] = ffma2(ap1, wv[i], accB[1][i]);
        }
    }
    #pragma unroll
    for (int j = 0; j < 2; j++)
        #pragma unroll
        for (int i = 0; i < 4; i++) {
            float2 u = unpack2(accB[j][i]);
            float* d = &sHid[(ttb * 2 + j) * 129 + oo * 8 + 2 * i];
            d[0] = fmaxf(u.x + sb1[oo * 8 + 2 * i], 0.f);
            d[1] = fmaxf(u.y + sb1[oo * 8 + 2 * i + 1], 0.f);
        }
    __syncthreads();

    // ---- stage C: out = h2 + hid @ W2 + b2 ----
    u64 accC[2] = {0, 0};
    #pragma unroll 4
    for (int k = 0; k < 128; k++) {
        float a = sHid[tr * 129 + k];
        u64 ap = pack2(a, a);
        ulonglong2 w0 = *(const ulonglong2*)&sW2[k * 32 + c0];
        accC[0] = ffma2(ap, w0.x, accC[0]);
        accC[1] = ffma2(ap, w0.y, accC[1]);
    }
    float2 u0 = unpack2(accC[0]), u1 = unpack2(accC[1]);
    *(float4*)(out + gt * 32 + c0) = make_float4(
        h2r[0] + u0.x + sB[32 + c0 + 0],
        h2r[1] + u0.y + sB[32 + c0 + 1],
        h2r[2] + u1.x + sB[32 + c0 + 2],
        h2r[3] + u1.y + sB[32 + c0 + 3]);
}

// ---------------------------------------------------------------------------
extern "C" void kernel_launch(void* const* d_in, const int* in_sizes, int n_in,
                              void* d_out, int out_size)
{
    const float* x   = (const float*)d_in[0];
    const float* Wq  = (const float*)d_in[1];
    const float* Wk  = (const float*)d_in[2];
    const float* Wv  = (const float*)d_in[3];
    const float* Wp  = (const float*)d_in[4];
    const float* bp  = (const float*)d_in[5];
    const float* g1  = (const float*)d_in[6];
    const float* b1  = (const float*)d_in[7];
    const float* W1  = (const float*)d_in[8];
    const float* b1f = (const float*)d_in[9];
    const float* W2  = (const float*)d_in[10];
    const float* b2f = (const float*)d_in[11];
    const float* g2  = (const float*)d_in[12];
    const float* bt2 = (const float*)d_in[13];
    float* out = (float*)d_out;

    cudaFuncSetAttribute((const void*)k_post,
                         cudaFuncAttributeMaxDynamicSharedMemorySize, SM3_BYTES);

    k_ln_qkv<<<BT_ / 16, 128>>>(x, Wq, Wk, Wv, g1, b1);

    dim3 ga(B_ * 4, 32);
    k_attn<<<ga, 64>>>();

    k_post<<<BT_ / 32, 256, SM3_BYTES>>>(out, Wp, bp, W1, b1f, W2, b2f, g2, bt2);
}

// round 7
// speedup vs baseline: 1.1504x; 1.1504x over previous
#include <cuda_runtime.h>

// ---------------------------------------------------------------------------
// DecoderBlock: x:(8,2048,32), H=4, hd=8. fp32, f32x2 packed FMA.
// Attention: causal-balanced pairing — block (bh, j) handles query tiles
// j and 15-j; 3-way key-tile parity split inside the block (384 threads).
// ---------------------------------------------------------------------------

constexpr int B_  = 8;
constexpr int T_  = 2048;
constexpr int D_  = 32;
constexpr int BT_ = B_ * T_;

__device__ float g_h[BT_ * D_];   // LN1 output
__device__ float g_q[BT_ * D_];   // (B,H,T,8), pre-scaled by log2e/sqrt(8)
__device__ float g_k[BT_ * D_];
__device__ float g_v[BT_ * D_];
__device__ float g_o[BT_ * D_];   // attention out (B*T,32), normalized

typedef unsigned long long u64;

static __device__ __forceinline__ u64 ffma2(u64 a, u64 b, u64 c) {
    u64 d; asm("fma.rn.f32x2 %0, %1, %2, %3;" : "=l"(d) : "l"(a), "l"(b), "l"(c));
    return d;
}
static __device__ __forceinline__ u64 fmul2(u64 a, u64 b) {
    u64 d; asm("mul.rn.f32x2 %0, %1, %2;" : "=l"(d) : "l"(a), "l"(b));
    return d;
}
static __device__ __forceinline__ u64 fadd2(u64 a, u64 b) {
    u64 d; asm("add.rn.f32x2 %0, %1, %2;" : "=l"(d) : "l"(a), "l"(b));
    return d;
}
static __device__ __forceinline__ u64 pack2(float x, float y) {
    u64 d; asm("mov.b64 %0, {%1, %2};" : "=l"(d) : "f"(x), "f"(y));
    return d;
}
static __device__ __forceinline__ float2 unpack2(u64 d) {
    float2 r; asm("mov.b64 {%0, %1}, %2;" : "=f"(r.x), "=f"(r.y) : "l"(d));
    return r;
}
static __device__ __forceinline__ float ex2f(float x) {
    float r; asm("ex2.approx.ftz.f32 %0, %1;" : "=f"(r) : "f"(x));
    return r;
}

// ---------------------------------------------------------------------------
// Kernel 1: LN1 + QKV. 32 tokens/block, 128 threads, grid 512.
// ---------------------------------------------------------------------------
__global__ __launch_bounds__(128) void k_ln_qkv(
    const float* __restrict__ x,
    const float* __restrict__ Wq, const float* __restrict__ Wk,
    const float* __restrict__ Wv,
    const float* __restrict__ g1, const float* __restrict__ b1)
{
    __shared__ __align__(16) float sh_h[32][33];
    __shared__ __align__(16) float sh_w[32][96];   // [d][qkv*32 + head*8 + kk]

    const int tid = threadIdx.x;
    const int t0  = blockIdx.x * 32;

    // stage qkv weights, vectorized: 768 float4 in 6 rounds
    for (int i4 = tid; i4 < 768; i4 += 128) {
        int i = i4 * 4;
        int type = i >> 10, rem = i & 1023;
        int head = rem >> 8, d = (rem >> 3) & 31, kk = rem & 7;
        const float* W = (type == 0) ? Wq : (type == 1) ? Wk : Wv;
        *(float4*)&sh_w[d][type * 32 + head * 8 + kk] = *(const float4*)(W + rem);
    }

    // LN: 4 lanes per token
    const int tk = tid >> 2, part = tid & 3;
    const int t  = t0 + tk;
    const int c0 = part * 8;
    const float4* xr = (const float4*)(x + t * 32 + c0);
    float4 v0 = xr[0], v1 = xr[1];
    float s  = v0.x + v0.y + v0.z + v0.w + v1.x + v1.y + v1.z + v1.w;
    float ss = v0.x*v0.x + v0.y*v0.y + v0.z*v0.z + v0.w*v0.w
             + v1.x*v1.x + v1.y*v1.y + v1.z*v1.z + v1.w*v1.w;
    s  += __shfl_xor_sync(0xffffffffu, s, 1);
    ss += __shfl_xor_sync(0xffffffffu, ss, 1);
    s  += __shfl_xor_sync(0xffffffffu, s, 2);
    ss += __shfl_xor_sync(0xffffffffu, ss, 2);
    const float mu = s * 0.03125f;
    const float rs = rsqrtf(ss * 0.03125f - mu * mu + 1e-5f);
    float hv[8];
    {
        const float* vv = (const float*)&v0;
        #pragma unroll
        for (int i = 0; i < 4; i++)
            hv[i] = (vv[i] - mu) * rs * __ldg(g1 + c0 + i) + __ldg(b1 + c0 + i);
        const float* vw = (const float*)&v1;
        #pragma unroll
        for (int i = 0; i < 4; i++)
            hv[4 + i] = (vw[i] - mu) * rs * __ldg(g1 + c0 + 4 + i) + __ldg(b1 + c0 + 4 + i);
    }
    #pragma unroll
    for (int i = 0; i < 8; i++) sh_h[tk][c0 + i] = hv[i];
    float4* hr = (float4*)(g_h + t * 32 + c0);
    hr[0] = make_float4(hv[0], hv[1], hv[2], hv[3]);
    hr[1] = make_float4(hv[4], hv[5], hv[6], hv[7]);
    __syncthreads();

    // GEMM: thread = 2 tokens x 12 outs (packed pairs)
    const int to = tid >> 3;   // 0..15
    const int oo = tid & 7;    // 0..7
    u64 acc0[6] = {0,0,0,0,0,0}, acc1[6] = {0,0,0,0,0,0};

    #pragma unroll 4
    for (int kd = 0; kd < 32; kd++) {
        float a0 = sh_h[2 * to][kd];
        float a1 = sh_h[2 * to + 1][kd];
        u64 ap0 = pack2(a0, a0), ap1 = pack2(a1, a1);
        const ulonglong2* wr = (const ulonglong2*)&sh_w[kd][oo * 12];
        ulonglong2 w0 = wr[0], w1 = wr[1], w2 = wr[2];
        u64 wv[6] = {w0.x, w0.y, w1.x, w1.y, w2.x, w2.y};
        #pragma unroll
        for (int i = 0; i < 6; i++) {
            acc0[i] = ffma2(ap0, wv[i], acc0[i]);
            acc1[i] = ffma2(ap1, wv[i], acc1[i]);
        }
    }

    const float QS = 0.51006973f;            // log2(e)/sqrt(8)
    const int b   = t0 >> 11;
    const int ttl = (t0 & 2047) + 2 * to;
    #pragma unroll
    for (int i2 = 0; i2 < 6; i2++) {
        int o    = oo * 12 + 2 * i2;
        int type = o >> 5;
        int head = (o >> 3) & 3;
        int kk   = o & 7;
        float* base = (type == 0) ? g_q : (type == 1) ? g_k : g_v;
        float sc = (type == 0) ? QS : 1.f;
        float2 u0 = unpack2(acc0[i2]);
        float2 u1 = unpack2(acc1[i2]);
        float* p = base + ((b * 4 + head) * 2048 + ttl) * 8 + kk;
        *(float2*)(p)     = make_float2(u0.x * sc, u0.y * sc);
        *(float2*)(p + 8) = make_float2(u1.x * sc, u1.y * sc);
    }
}

// ---------------------------------------------------------------------------
// Kernel 2: causal attention, balanced pairing, 3-way key-parity split.
// grid (32, 8), 384 threads. Block (bh, j): query tiles j and 15-j.
// Group g = tid/128 handles key tiles kt ≡ g (mod 3); additive partials
// merged via smem at the end.
// ---------------------------------------------------------------------------
static __device__ __forceinline__ void attn_pair(
    const u64* __restrict__ q, const ulonglong2& kA, const ulonglong2& kB,
    const ulonglong2& kC, const ulonglong2& kD,
    const ulonglong2& va0, const ulonglong2& va1,
    const ulonglong2& vb0, const ulonglong2& vb1,
    u64* __restrict__ o, float& l, bool m0, bool m1)
{
    u64 e = fmul2(q[0], kA.x); e = ffma2(q[2], kB.x, e);
    e = ffma2(q[4], kC.x, e);  e = ffma2(q[6], kD.x, e);
    u64 od = fmul2(q[1], kA.y); od = ffma2(q[3], kB.y, od);
    od = ffma2(q[5], kC.y, od); od = ffma2(q[7], kD.y, od);
    float2 d = unpack2(fadd2(e, od));
    float p0 = m0 ? ex2f(d.x) : 0.f;
    float p1 = m1 ? ex2f(d.y) : 0.f;
    l += p0 + p1;
    u64 pp0 = pack2(p0, p0), pp1 = pack2(p1, p1);
    o[0] = ffma2(pp0, va0.x, o[0]); o[1] = ffma2(pp0, va0.y, o[1]);
    o[2] = ffma2(pp0, va1.x, o[2]); o[3] = ffma2(pp0, va1.y, o[3]);
    o[0] = ffma2(pp1, vb0.x, o[0]); o[1] = ffma2(pp1, vb0.y, o[1]);
    o[2] = ffma2(pp1, vb1.x, o[2]); o[3] = ffma2(pp1, vb1.y, o[3]);
}

__global__ __launch_bounds__(384) void k_attn()
{
    __shared__ __align__(16) u64    sKp[3][640];    // [grp][keypair*10 + dim]
    __shared__ __align__(16) float4 sV [3][256];    // [grp][key*2 + dimhalf]
    __shared__ float sPart[2][128 * 20];            // groups 1,2 partials

    const int tid  = threadIdx.x;
    const int grp  = tid >> 7;         // 0..2 = key-tile parity (mod 3)
    const int ht   = tid & 127;
    const int bh   = blockIdx.x;
    const int j    = blockIdx.y;       // 0..7 -> tiles j and 15-j
    const int jhi  = 15 - j;
    const int tqa  = j * 128 + ht;
    const int tqb  = jhi * 128 + ht;

    u64 qa[8], qq[8];
    {
        const float4* pa = (const float4*)(g_q + (bh * T_ + tqa) * 8);
        float4 a0 = pa[0], a1 = pa[1];
        qa[0]=pack2(a0.x,a0.x); qa[1]=pack2(a0.y,a0.y); qa[2]=pack2(a0.z,a0.z); qa[3]=pack2(a0.w,a0.w);
        qa[4]=pack2(a1.x,a1.x); qa[5]=pack2(a1.y,a1.y); qa[6]=pack2(a1.z,a1.z); qa[7]=pack2(a1.w,a1.w);
        const float4* pb = (const float4*)(g_q + (bh * T_ + tqb) * 8);
        float4 b0 = pb[0], b1 = pb[1];
        qq[0]=pack2(b0.x,b0.x); qq[1]=pack2(b0.y,b0.y); qq[2]=pack2(b0.z,b0.z); qq[3]=pack2(b0.w,b0.w);
        qq[4]=pack2(b1.x,b1.x); qq[5]=pack2(b1.y,b1.y); qq[6]=pack2(b1.z,b1.z); qq[7]=pack2(b1.w,b1.w);
    }

    u64 oa[4] = {0,0,0,0}, ob[4] = {0,0,0,0};
    float la = 0.f, lb = 0.f;

    const float4* vb4 = (const float4*)(g_v + bh * T_ * 8);
    const int bar = 1 + grp;

    for (int kt = grp; kt <= jhi; kt += 3) {
        const int s0 = kt * 128;
        {   // stage K transposed+key-paired: 2 threads per key pair
            const int t2 = ht >> 6, sp = ht & 63;
            const float4* kg = (const float4*)(g_k + (bh * T_ + s0 + 2 * sp) * 8 + t2 * 4);
            float4 ka = kg[0];       // key 2sp, 4 dims
            float4 kb = kg[2];       // key 2sp+1
            u64* row = (u64*)&sKp[grp][sp * 10 + t2 * 4];
            row[0] = pack2(ka.x, kb.x); row[1] = pack2(ka.y, kb.y);
            row[2] = pack2(ka.z, kb.z); row[3] = pack2(ka.w, kb.w);
            sV[grp][ht]       = vb4[s0 * 2 + ht];
            sV[grp][ht + 128] = vb4[s0 * 2 + ht + 128];
        }
        asm volatile("bar.sync %0, 128;" :: "r"(bar) : "memory");

        if (kt < j) {
            // both queries, full
            #pragma unroll 2
            for (int sp = 0; sp < 64; sp++) {
                const ulonglong2* kr = (const ulonglong2*)&sKp[grp][sp * 10];
                ulonglong2 kA = kr[0], kB = kr[1], kC = kr[2], kD = kr[3];
                const ulonglong2* vr = (const ulonglong2*)&sV[grp][4 * sp];
                ulonglong2 va0 = vr[0], va1 = vr[1], vb0 = vr[2], vb1 = vr[3];
                attn_pair(qa, kA, kB, kC, kD, va0, va1, vb0, vb1, oa, la, true, true);
                attn_pair(qq, kA, kB, kC, kD, va0, va1, vb0, vb1, ob, lb, true, true);
            }
        } else if (kt == j) {
            // qa diagonal, qb full
            for (int sp = 0; sp < 64; sp++) {
                const ulonglong2* kr = (const ulonglong2*)&sKp[grp][sp * 10];
                ulonglong2 kA = kr[0], kB = kr[1], kC = kr[2], kD = kr[3];
                const ulonglong2* vr = (const ulonglong2*)&sV[grp][4 * sp];
                ulonglong2 va0 = vr[0], va1 = vr[1], vb0 = vr[2], vb1 = vr[3];
                attn_pair(qa, kA, kB, kC, kD, va0, va1, vb0, vb1, oa, la,
                          2 * sp <= ht, 2 * sp + 1 <= ht);
                attn_pair(qq, kA, kB, kC, kD, va0, va1, vb0, vb1, ob, lb, true, true);
            }
        } else if (kt < jhi) {
            // qb only, full
            #pragma unroll 2
            for (int sp = 0; sp < 64; sp++) {
                const ulonglong2* kr = (const ulonglong2*)&sKp[grp][sp * 10];
                ulonglong2 kA = kr[0], kB = kr[1], kC = kr[2], kD = kr[3];
                const ulonglong2* vr = (const ulonglong2*)&sV[grp][4 * sp];
                ulonglong2 va0 = vr[0], va1 = vr[1], vb0 = vr[2], vb1 = vr[3];
                attn_pair(qq, kA, kB, kC, kD, va0, va1, vb0, vb1, ob, lb, true, true);
            }
        } else {
            // qb diagonal
            for (int sp = 0; sp < 64; sp++) {
                const ulonglong2* kr = (const ulonglong2*)&sKp[grp][sp * 10];
                ulonglong2 kA = kr[0], kB = kr[1], kC = kr[2], kD = kr[3];
                const ulonglong2* vr = (const ulonglong2*)&sV[grp][4 * sp];
                ulonglong2 va0 = vr[0], va1 = vr[1], vb0 = vr[2], vb1 = vr[3];
                attn_pair(qq, kA, kB, kC, kD, va0, va1, vb0, vb1, ob, lb,
                          2 * sp <= ht, 2 * sp + 1 <= ht);
            }
        }
        asm volatile("bar.sync %0, 128;" :: "r"(bar) : "memory");
    }

    if (grp > 0) {
        float* pb = &sPart[grp - 1][ht * 20];
        #pragma unroll
        for (int i = 0; i < 4; i++) {
            float2 u = unpack2(oa[i]); pb[2*i] = u.x; pb[2*i+1] = u.y;
            float2 w = unpack2(ob[i]); pb[8+2*i] = w.x; pb[8+2*i+1] = w.y;
        }
        pb[16] = la; pb[17] = lb;
    }
    __syncthreads();
    if (grp == 0) {
        const float* p1 = &sPart[0][ht * 20];
        const float* p2 = &sPart[1][ht * 20];
        float oav[8], obv[8];
        #pragma unroll
        for (int i = 0; i < 4; i++) {
            float2 u = unpack2(oa[i]);
            oav[2*i]   = u.x + p1[2*i]   + p2[2*i];
            oav[2*i+1] = u.y + p1[2*i+1] + p2[2*i+1];
            float2 w = unpack2(ob[i]);
            obv[2*i]   = w.x + p1[8+2*i]   + p2[8+2*i];
            obv[2*i+1] = w.y + p1[8+2*i+1] + p2[8+2*i+1];
        }
        const float ra = __fdividef(1.f, la + p1[16] + p2[16]);
        const float rb = __fdividef(1.f, lb + p1[17] + p2[17]);
        const int b = bh >> 2, h = bh & 3;
        float4* opa = (float4*)(g_o + (b * T_ + tqa) * 32 + h * 8);
        opa[0] = make_float4(oav[0]*ra, oav[1]*ra, oav[2]*ra, oav[3]*ra);
        opa[1] = make_float4(oav[4]*ra, oav[5]*ra, oav[6]*ra, oav[7]*ra);
        float4* opb = (float4*)(g_o + (b * T_ + tqb) * 32 + h * 8);
        opb[0] = make_float4(obv[0]*rb, obv[1]*rb, obv[2]*rb, obv[3]*rb);
        opb[1] = make_float4(obv[4]*rb, obv[5]*rb, obv[6]*rb, obv[7]*rb);
    }
}

// ---------------------------------------------------------------------------
// Kernel 3: proj + residual + LN2 + FFN + residual. 32 tokens, 256 threads,
// grid 512.
// ---------------------------------------------------------------------------
constexpr int SM3_FLOATS = 1024 + 4096 + 4096 + 128 + 128 + 32 * 33 + 32 * 129;
constexpr int SM3_BYTES  = SM3_FLOATS * 4;   // ~57.3 KB

__global__ __launch_bounds__(256) void k_post(
    float* __restrict__ out,
    const float* __restrict__ Wp, const float* __restrict__ bp,
    const float* __restrict__ W1, const float* __restrict__ b1v,
    const float* __restrict__ W2, const float* __restrict__ b2v,
    const float* __restrict__ g2, const float* __restrict__ bt2)
{
    extern __shared__ float sm[];
    float* sWp  = sm;                 // [kd][32]
    float* sW1  = sWp + 1024;         // [k][128]
    float* sW2  = sW1 + 4096;         // [k][32]
    float* sB   = sW2 + 4096;         // 0:bproj 32:b2 64:ln2_g 96:ln2_b
    float* sb1  = sB + 128;
    float* sX   = sb1 + 128;          // 32 x 33
    float* sHid = sX + 32 * 33;       // 32 x 129

    const int tid = threadIdx.x;
    const int t0  = blockIdx.x * 32;

    // vectorized weight staging
    *(float4*)&sWp[tid * 4] = *(const float4*)(Wp + tid * 4);
    for (int i4 = tid; i4 < 1024; i4 += 256)
        *(float4*)&sW1[i4 * 4] = *(const float4*)(W1 + i4 * 4);
    for (int i4 = tid; i4 < 1024; i4 += 256)
        *(float4*)&sW2[i4 * 4] = *(const float4*)(W2 + i4 * 4);
    if (tid < 32) { sB[tid] = bp[tid]; sB[32 + tid] = b2v[tid];
                    sB[64 + tid] = g2[tid]; sB[96 + tid] = bt2[tid]; }
    if (tid >= 128 && tid < 256) sb1[tid - 128] = b1v[tid - 128];

    {   // o tile -> sX  (32 tokens x 8 float4 = 256 = one per thread)
        int row = tid >> 3, c4 = tid & 7;
        float4 v = ((const float4*)(g_o + (t0 + row) * 32))[c4];
        float* d = &sX[row * 33 + c4 * 4];
        d[0] = v.x; d[1] = v.y; d[2] = v.z; d[3] = v.w;
    }
    __syncthreads();

    // ---- stage A: x1 = h + o@Wproj + bproj ; h2 = LN2(x1) ----
    const int tr = tid >> 3, q8 = tid & 7;   // token, col-eighth (4 cols)
    const int c0 = q8 * 4;
    const int gt = t0 + tr;
    u64 accp[2] = {0, 0};

    #pragma unroll 4
    for (int kd = 0; kd < 32; kd++) {
        float a = sX[tr * 33 + kd];
        u64 ap = pack2(a, a);
        ulonglong2 w0 = *(const ulonglong2*)&sWp[kd * 32 + c0];
        accp[0] = ffma2(ap, w0.x, accp[0]);
        accp[1] = ffma2(ap, w0.y, accp[1]);
    }
    float xv[4];
    {
        float4 h0 = *(const float4*)(g_h + gt * 32 + c0);
        float2 u0 = unpack2(accp[0]), u1 = unpack2(accp[1]);
        xv[0] = h0.x + u0.x + sB[c0 + 0];
        xv[1] = h0.y + u0.y + sB[c0 + 1];
        xv[2] = h0.z + u1.x + sB[c0 + 2];
        xv[3] = h0.w + u1.y + sB[c0 + 3];
    }
    float s = 0.f, ss = 0.f;
    #pragma unroll
    for (int i = 0; i < 4; i++) { s += xv[i]; ss += xv[i] * xv[i]; }
    s  += __shfl_xor_sync(0xffffffffu, s, 1);
    ss += __shfl_xor_sync(0xffffffffu, ss, 1);
    s  += __shfl_xor_sync(0xffffffffu, s, 2);
    ss += __shfl_xor_sync(0xffffffffu, ss, 2);
    s  += __shfl_xor_sync(0xffffffffu, s, 4);
    ss += __shfl_xor_sync(0xffffffffu, ss, 4);
    const float mu = s * 0.03125f;
    const float rs = rsqrtf(ss * 0.03125f - mu * mu + 1e-5f);
    float h2r[4];
    #pragma unroll
    for (int i = 0; i < 4; i++)
        h2r[i] = (xv[i] - mu) * rs * sB[64 + c0 + i] + sB[96 + c0 + i];

    __syncthreads();                 // all o-tile reads done; reuse sX for h2
    #pragma unroll
    for (int i = 0; i < 4; i++) sX[tr * 33 + c0 + i] = h2r[i];
    __syncthreads();

    // ---- stage B: hid = relu(h2 @ W1 + b1) ----
    const int ttb = tid >> 4;   // 0..15 -> 2 tokens each
    const int oo  = tid & 15;   // 8 outs each
    u64 accB[2][4];
    #pragma unroll
    for (int j = 0; j < 2; j++)
        #pragma unroll
        for (int i = 0; i < 4; i++) accB[j][i] = 0;

    #pragma unroll 4
    for (int k = 0; k < 32; k++) {
        float a0 = sX[(ttb * 2 + 0) * 33 + k];
        float a1 = sX[(ttb * 2 + 1) * 33 + k];
        u64 ap0 = pack2(a0, a0), ap1 = pack2(a1, a1);
        const ulonglong2* wr = (const ulonglong2*)&sW1[k * 128 + oo * 8];
        ulonglong2 ww0 = wr[0], ww1 = wr[1];
        u64 wv[4] = {ww0.x, ww0.y, ww1.x, ww1.y};
        #pragma unroll
        for (int i = 0; i < 4; i++) {
            accB[0][i] = ffma2(ap0, wv[i], accB[0][i]);
            accB[1][i] = ffma2(ap1, wv[i], accB[1][i]);
        }
    }
    #pragma unroll
    for (int j = 0; j < 2; j++)
        #pragma unroll
        for (int i = 0; i < 4; i++) {
            float2 u = unpack2(accB[j][i]);
            float* d = &sHid[(ttb * 2 + j) * 129 + oo * 8 + 2 * i];
            d[0] = fmaxf(u.x + sb1[oo * 8 + 2 * i], 0.f);
            d[1] = fmaxf(u.y + sb1[oo * 8 + 2 * i + 1], 0.f);
        }
    __syncthreads();

    // ---- stage C: out = h2 + hid @ W2 + b2 ----
    u64 accC[2] = {0, 0};
    #pragma unroll 4
    for (int k = 0; k < 128; k++) {
        float a = sHid[tr * 129 + k];
        u64 ap = pack2(a, a);
        ulonglong2 w0 = *(const ulonglong2*)&sW2[k * 32 + c0];
        accC[0] = ffma2(ap, w0.x, accC[0]);
        accC[1] = ffma2(ap, w0.y, accC[1]);
    }
    float2 u0 = unpack2(accC[0]), u1 = unpack2(accC[1]);
    *(float4*)(out + gt * 32 + c0) = make_float4(
        h2r[0] + u0.x + sB[32 + c0 + 0],
        h2r[1] + u0.y + sB[32 + c0 + 1],
        h2r[2] + u1.x + sB[32 + c0 + 2],
        h2r[3] + u1.y + sB[32 + c0 + 3]);
}

// ---------------------------------------------------------------------------
extern "C" void kernel_launch(void* const* d_in, const int* in_sizes, int n_in,
                              void* d_out, int out_size)
{
    const float* x   = (const float*)d_in[0];
    const float* Wq  = (const float*)d_in[1];
    const float* Wk  = (const float*)d_in[2];
    const float* Wv  = (const float*)d_in[3];
    const float* Wp  = (const float*)d_in[4];
    const float* bp  = (const float*)d_in[5];
    const float* g1  = (const float*)d_in[6];
    const float* b1  = (const float*)d_in[7];
    const float* W1  = (const float*)d_in[8];
    const float* b1f = (const float*)d_in[9];
    const float* W2  = (const float*)d_in[10];
    const float* b2f = (const float*)d_in[11];
    const float* g2  = (const float*)d_in[12];
    const float* bt2 = (const float*)d_in[13];
    float* out = (float*)d_out;

    cudaFuncSetAttribute((const void*)k_post,
                         cudaFuncAttributeMaxDynamicSharedMemorySize, SM3_BYTES);

    k_ln_qkv<<<BT_ / 32, 128>>>(x, Wq, Wk, Wv, g1, b1);

    dim3 ga(B_ * 4, 8);
    k_attn<<<ga, 384>>>();

    k_post<<<BT_ / 32, 256, SM3_BYTES>>>(out, Wp, bp, W1, b1f, W2, b2f, g2, bt2);
}

// round 8
// speedup vs baseline: 1.7864x; 1.5528x over previous
#include <cuda_runtime.h>
#include <cuda_fp16.h>

// ---------------------------------------------------------------------------
// DecoderBlock: x:(8,2048,32), H=4, hd=8.
// LN/QKV/post: fp32 f32x2 SIMT. Attention: tensor cores —
// QK^T via mma.m16n8k8.tf32, PV via mma.m16n8k16.f16 (fp32 accum),
// balanced causal pairing (block (bh,j) owns query tiles j and 15-j).
// ---------------------------------------------------------------------------

constexpr int B_  = 8;
constexpr int T_  = 2048;
constexpr int D_  = 32;
constexpr int BT_ = B_ * T_;

__device__ float g_h[BT_ * D_];   // LN1 output
__device__ float g_q[BT_ * D_];   // (B,H,T,8), pre-scaled by log2e/sqrt(8)
__device__ float g_k[BT_ * D_];
__device__ float g_v[BT_ * D_];
__device__ float g_o[BT_ * D_];   // attention out (B*T,32), normalized

typedef unsigned long long u64;
typedef unsigned int u32;

static __device__ __forceinline__ u64 ffma2(u64 a, u64 b, u64 c) {
    u64 d; asm("fma.rn.f32x2 %0, %1, %2, %3;" : "=l"(d) : "l"(a), "l"(b), "l"(c));
    return d;
}
static __device__ __forceinline__ u64 pack2(float x, float y) {
    u64 d; asm("mov.b64 %0, {%1, %2};" : "=l"(d) : "f"(x), "f"(y));
    return d;
}
static __device__ __forceinline__ float2 unpack2(u64 d) {
    float2 r; asm("mov.b64 {%0, %1}, %2;" : "=f"(r.x), "=f"(r.y) : "l"(d));
    return r;
}
static __device__ __forceinline__ float ex2f(float x) {
    float r; asm("ex2.approx.ftz.f32 %0, %1;" : "=f"(r) : "f"(x));
    return r;
}
static __device__ __forceinline__ u32 cvt_tf32(float f) {
    u32 u; asm("cvt.rna.tf32.f32 %0, %1;" : "=r"(u) : "f"(f));
    return u;
}
static __device__ __forceinline__ u32 pack_h2(float lo, float hi) {
    __half2 h = __floats2half2_rn(lo, hi);
    u32 u; __builtin_memcpy(&u, &h, 4);
    return u;
}
// S = Q(16x8) * K^T(8x8), tf32, C initialized to zero.
static __device__ __forceinline__ void mma_tf32_zero(float* d, const u32* a, const u32* b) {
    asm("mma.sync.aligned.m16n8k8.row.col.f32.tf32.tf32.f32 "
        "{%0,%1,%2,%3}, {%4,%5,%6,%7}, {%8,%9}, {%10,%11,%12,%13};"
        : "=f"(d[0]), "=f"(d[1]), "=f"(d[2]), "=f"(d[3])
        : "r"(a[0]), "r"(a[1]), "r"(a[2]), "r"(a[3]),
          "r"(b[0]), "r"(b[1]),
          "f"(0.f), "f"(0.f), "f"(0.f), "f"(0.f));
}
// O += P(16x16,f16) * V(16x8,f16), fp32 accumulate.
static __device__ __forceinline__ void mma_f16(float* d, const u32* a, const u32* b) {
    asm("mma.sync.aligned.m16n8k16.row.col.f32.f16.f16.f32 "
        "{%0,%1,%2,%3}, {%4,%5,%6,%7}, {%8,%9}, {%0,%1,%2,%3};"
        : "+f"(d[0]), "+f"(d[1]), "+f"(d[2]), "+f"(d[3])
        : "r"(a[0]), "r"(a[1]), "r"(a[2]), "r"(a[3]),
          "r"(b[0]), "r"(b[1]));
}

// ---------------------------------------------------------------------------
// Kernel 1: LN1 + QKV. 32 tokens/block, 128 threads, grid 512. (unchanged)
// ---------------------------------------------------------------------------
__global__ __launch_bounds__(128) void k_ln_qkv(
    const float* __restrict__ x,
    const float* __restrict__ Wq, const float* __restrict__ Wk,
    const float* __restrict__ Wv,
    const float* __restrict__ g1, const float* __restrict__ b1)
{
    __shared__ __align__(16) float sh_h[32][33];
    __shared__ __align__(16) float sh_w[32][96];   // [d][qkv*32 + head*8 + kk]

    const int tid = threadIdx.x;
    const int t0  = blockIdx.x * 32;

    for (int i4 = tid; i4 < 768; i4 += 128) {
        int i = i4 * 4;
        int type = i >> 10, rem = i & 1023;
        int head = rem >> 8, d = (rem >> 3) & 31, kk = rem & 7;
        const float* W = (type == 0) ? Wq : (type == 1) ? Wk : Wv;
        *(float4*)&sh_w[d][type * 32 + head * 8 + kk] = *(const float4*)(W + rem);
    }

    const int tk = tid >> 2, part = tid & 3;
    const int t  = t0 + tk;
    const int c0 = part * 8;
    const float4* xr = (const float4*)(x + t * 32 + c0);
    float4 v0 = xr[0], v1 = xr[1];
    float s  = v0.x + v0.y + v0.z + v0.w + v1.x + v1.y + v1.z + v1.w;
    float ss = v0.x*v0.x + v0.y*v0.y + v0.z*v0.z + v0.w*v0.w
             + v1.x*v1.x + v1.y*v1.y + v1.z*v1.z + v1.w*v1.w;
    s  += __shfl_xor_sync(0xffffffffu, s, 1);
    ss += __shfl_xor_sync(0xffffffffu, ss, 1);
    s  += __shfl_xor_sync(0xffffffffu, s, 2);
    ss += __shfl_xor_sync(0xffffffffu, ss, 2);
    const float mu = s * 0.03125f;
    const float rs = rsqrtf(ss * 0.03125f - mu * mu + 1e-5f);
    float hv[8];
    {
        const float* vv = (const float*)&v0;
        #pragma unroll
        for (int i = 0; i < 4; i++)
            hv[i] = (vv[i] - mu) * rs * __ldg(g1 + c0 + i) + __ldg(b1 + c0 + i);
        const float* vw = (const float*)&v1;
        #pragma unroll
        for (int i = 0; i < 4; i++)
            hv[4 + i] = (vw[i] - mu) * rs * __ldg(g1 + c0 + 4 + i) + __ldg(b1 + c0 + 4 + i);
    }
    #pragma unroll
    for (int i = 0; i < 8; i++) sh_h[tk][c0 + i] = hv[i];
    float4* hr = (float4*)(g_h + t * 32 + c0);
    hr[0] = make_float4(hv[0], hv[1], hv[2], hv[3]);
    hr[1] = make_float4(hv[4], hv[5], hv[6], hv[7]);
    __syncthreads();

    const int to = tid >> 3;
    const int oo = tid & 7;
    u64 acc0[6] = {0,0,0,0,0,0}, acc1[6] = {0,0,0,0,0,0};

    #pragma unroll 4
    for (int kd = 0; kd < 32; kd++) {
        float a0 = sh_h[2 * to][kd];
        float a1 = sh_h[2 * to + 1][kd];
        u64 ap0 = pack2(a0, a0), ap1 = pack2(a1, a1);
        const ulonglong2* wr = (const ulonglong2*)&sh_w[kd][oo * 12];
        ulonglong2 w0 = wr[0], w1 = wr[1], w2 = wr[2];
        u64 wv[6] = {w0.x, w0.y, w1.x, w1.y, w2.x, w2.y};
        #pragma unroll
        for (int i = 0; i < 6; i++) {
            acc0[i] = ffma2(ap0, wv[i], acc0[i]);
            acc1[i] = ffma2(ap1, wv[i], acc1[i]);
        }
    }

    const float QS = 0.51006973f;            // log2(e)/sqrt(8)
    const int b   = t0 >> 11;
    const int ttl = (t0 & 2047) + 2 * to;
    #pragma unroll
    for (int i2 = 0; i2 < 6; i2++) {
        int o    = oo * 12 + 2 * i2;
        int type = o >> 5;
        int head = (o >> 3) & 3;
        int kk   = o & 7;
        float* base = (type == 0) ? g_q : (type == 1) ? g_k : g_v;
        float sc = (type == 0) ? QS : 1.f;
        float2 u0 = unpack2(acc0[i2]);
        float2 u1 = unpack2(acc1[i2]);
        float* p = base + ((b * 4 + head) * 2048 + ttl) * 8 + kk;
        *(float2*)(p)     = make_float2(u0.x * sc, u0.y * sc);
        *(float2*)(p + 8) = make_float2(u1.x * sc, u1.y * sc);
    }
}

// ---------------------------------------------------------------------------
// Kernel 2: causal attention with tensor cores.
// grid (32, 8), 256 threads (8 warps). Warp w owns query rows [16w,16w+16)
// of tiles j*128 (qa) and (15-j)*128 (qb). Loop key tiles kt=0..15-j.
// ---------------------------------------------------------------------------
__shared__ u32 sK_attn_dummy;   // (placed in kernel; dummy avoids empty)

static __device__ __forceinline__ void attn_dchunk(
    const u32* __restrict__ qf, const u32 kb[2][2], const u32* __restrict__ vb,
    float* __restrict__ o, float& l0, float& l1,
    bool diag, int keybase, int r0, int tig2)
{
    float p[2][4];
    #pragma unroll
    for (int e = 0; e < 2; e++) {
        mma_tf32_zero(p[e], qf, kb[e]);
        p[e][0] = ex2f(p[e][0]); p[e][1] = ex2f(p[e][1]);
        p[e][2] = ex2f(p[e][2]); p[e][3] = ex2f(p[e][3]);
        if (diag) {
            int k0 = keybase + 8 * e + tig2;
            p[e][0] = (k0     <= r0)     ? p[e][0] : 0.f;
            p[e][1] = (k0 + 1 <= r0)     ? p[e][1] : 0.f;
            p[e][2] = (k0     <= r0 + 8) ? p[e][2] : 0.f;
            p[e][3] = (k0 + 1 <= r0 + 8) ? p[e][3] : 0.f;
        }
    }
    l0 += (p[0][0] + p[0][1]) + (p[1][0] + p[1][1]);
    l1 += (p[0][2] + p[0][3]) + (p[1][2] + p[1][3]);
    u32 a[4] = { pack_h2(p[0][0], p[0][1]), pack_h2(p[0][2], p[0][3]),
                 pack_h2(p[1][0], p[1][1]), pack_h2(p[1][2], p[1][3]) };
    mma_f16(o, a, vb);
}

__global__ __launch_bounds__(256) void k_attn()
{
    __shared__ u32 sK[128 * 12];   // tf32 K tile, row stride 12 (conflict-free)
    __shared__ u32 sV[8 * 68];     // half2 V: [dim][keypair], stride 68

    const int tid = threadIdx.x;
    const int w   = tid >> 5;          // warp 0..7
    const int ln  = tid & 31;
    const int g   = ln >> 2;           // groupID 0..7
    const int tig = ln & 3;            // 0..3
    const int bh  = blockIdx.x;
    const int j   = blockIdx.y;        // query tiles j and 15-j
    const int jhi = 15 - j;

    const float* Qg = g_q + bh * T_ * 8;
    const int qa0 = j   * 128 + w * 16 + g;   // this thread's qa row (and +8)
    const int qb0 = jhi * 128 + w * 16 + g;

    u32 qaf[4], qbf[4];
    qaf[0] = cvt_tf32(Qg[(qa0)     * 8 + tig]);
    qaf[1] = cvt_tf32(Qg[(qa0 + 8) * 8 + tig]);
    qaf[2] = cvt_tf32(Qg[(qa0)     * 8 + tig + 4]);
    qaf[3] = cvt_tf32(Qg[(qa0 + 8) * 8 + tig + 4]);
    qbf[0] = cvt_tf32(Qg[(qb0)     * 8 + tig]);
    qbf[1] = cvt_tf32(Qg[(qb0 + 8) * 8 + tig]);
    qbf[2] = cvt_tf32(Qg[(qb0)     * 8 + tig + 4]);
    qbf[3] = cvt_tf32(Qg[(qb0 + 8) * 8 + tig + 4]);

    float oa[4] = {0.f, 0.f, 0.f, 0.f}, ob[4] = {0.f, 0.f, 0.f, 0.f};
    float la0 = 0.f, la1 = 0.f, lb0 = 0.f, lb1 = 0.f;

    const int srow  = tid >> 1;        // staging row 0..127
    const int shalf = tid & 1;

    for (int kt = 0; kt <= jhi; kt++) {
        const int s0 = kt * 128;

        // ---- stage K (tf32, pad-12 rows) ----
        {
            float4 kv = *(const float4*)(g_k + (bh * T_ + s0 + srow) * 8 + shalf * 4);
            u32* kd = &sK[srow * 12 + shalf * 4];
            kd[0] = cvt_tf32(kv.x); kd[1] = cvt_tf32(kv.y);
            kd[2] = cvt_tf32(kv.z); kd[3] = cvt_tf32(kv.w);
        }
        // ---- stage V (half2 key pairs: [dim][keypair], stride 68) ----
        {
            float4 vv = *(const float4*)(g_v + (bh * T_ + s0 + srow) * 8 + shalf * 4);
            float px = __shfl_xor_sync(0xffffffffu, vv.x, 2);
            float py = __shfl_xor_sync(0xffffffffu, vv.y, 2);
            float pz = __shfl_xor_sync(0xffffffffu, vv.z, 2);
            float pw = __shfl_xor_sync(0xffffffffu, vv.w, 2);
            if ((tid & 2) == 0) {            // even row of the pair
                int kp = tid >> 2;
                int d0 = shalf * 4;
                sV[(d0 + 0) * 68 + kp] = pack_h2(vv.x, px);
                sV[(d0 + 1) * 68 + kp] = pack_h2(vv.y, py);
                sV[(d0 + 2) * 68 + kp] = pack_h2(vv.z, pz);
                sV[(d0 + 3) * 68 + kp] = pack_h2(vv.w, pw);
            }
        }
        __syncthreads();

        const bool qaAct = (kt <= j);
        const bool dA = (kt == j), dB = (kt == jhi);

        #pragma unroll 2
        for (int c = 0; c < 8; c++) {
            u32 kb[2][2];
            const u32* k0r = &sK[(16 * c + g) * 12];
            const u32* k1r = &sK[(16 * c + 8 + g) * 12];
            kb[0][0] = k0r[tig]; kb[0][1] = k0r[tig + 4];
            kb[1][0] = k1r[tig]; kb[1][1] = k1r[tig + 4];
            u32 vb[2];
            vb[0] = sV[g * 68 + 8 * c + tig];
            vb[1] = sV[g * 68 + 8 * c + tig + 4];

            if (qaAct)
                attn_dchunk(qaf, kb, vb, oa, la0, la1, dA, s0 + 16 * c, qa0, 2 * tig);
            attn_dchunk(qbf, kb, vb, ob, lb0, lb1, dB, s0 + 16 * c, qb0, 2 * tig);
        }
        __syncthreads();
    }

    // ---- finalize: reduce l over the quad, normalize, store ----
    la0 += __shfl_xor_sync(0xffffffffu, la0, 1);
    la0 += __shfl_xor_sync(0xffffffffu, la0, 2);
    la1 += __shfl_xor_sync(0xffffffffu, la1, 1);
    la1 += __shfl_xor_sync(0xffffffffu, la1, 2);
    lb0 += __shfl_xor_sync(0xffffffffu, lb0, 1);
    lb0 += __shfl_xor_sync(0xffffffffu, lb0, 2);
    lb1 += __shfl_xor_sync(0xffffffffu, lb1, 1);
    lb1 += __shfl_xor_sync(0xffffffffu, lb1, 2);
    const float ra0 = __fdividef(1.f, la0);
    const float ra1 = __fdividef(1.f, la1);
    const float rb0 = __fdividef(1.f, lb0);
    const float rb1 = __fdividef(1.f, lb1);

    const int bb = bh >> 2, h = bh & 3;
    const int colo = h * 8 + 2 * tig;
    *(float2*)(g_o + (bb * T_ + qa0)     * 32 + colo) = make_float2(oa[0] * ra0, oa[1] * ra0);
    *(float2*)(g_o + (bb * T_ + qa0 + 8) * 32 + colo) = make_float2(oa[2] * ra1, oa[3] * ra1);
    *(float2*)(g_o + (bb * T_ + qb0)     * 32 + colo) = make_float2(ob[0] * rb0, ob[1] * rb0);
    *(float2*)(g_o + (bb * T_ + qb0 + 8) * 32 + colo) = make_float2(ob[2] * rb1, ob[3] * rb1);
}

// ---------------------------------------------------------------------------
// Kernel 3: proj + residual + LN2 + FFN + residual. 32 tokens, 256 threads,
// grid 512. (unchanged)
// ---------------------------------------------------------------------------
constexpr int SM3_FLOATS = 1024 + 4096 + 4096 + 128 + 128 + 32 * 33 + 32 * 129;
constexpr int SM3_BYTES  = SM3_FLOATS * 4;

__global__ __launch_bounds__(256) void k_post(
    float* __restrict__ out,
    const float* __restrict__ Wp, const float* __restrict__ bp,
    const float* __restrict__ W1, const float* __restrict__ b1v,
    const float* __restrict__ W2, const float* __restrict__ b2v,
    const float* __restrict__ g2, const float* __restrict__ bt2)
{
    extern __shared__ float sm[];
    float* sWp  = sm;
    float* sW1  = sWp + 1024;
    float* sW2  = sW1 + 4096;
    float* sB   = sW2 + 4096;
    float* sb1  = sB + 128;
    float* sX   = sb1 + 128;
    float* sHid = sX + 32 * 33;

    const int tid = threadIdx.x;
    const int t0  = blockIdx.x * 32;

    *(float4*)&sWp[tid * 4] = *(const float4*)(Wp + tid * 4);
    for (int i4 = tid; i4 < 1024; i4 += 256)
        *(float4*)&sW1[i4 * 4] = *(const float4*)(W1 + i4 * 4);
    for (int i4 = tid; i4 < 1024; i4 += 256)
        *(float4*)&sW2[i4 * 4] = *(const float4*)(W2 + i4 * 4);
    if (tid < 32) { sB[tid] = bp[tid]; sB[32 + tid] = b2v[tid];
                    sB[64 + tid] = g2[tid]; sB[96 + tid] = bt2[tid]; }
    if (tid >= 128 && tid < 256) sb1[tid - 128] = b1v[tid - 128];

    {
        int row = tid >> 3, c4 = tid & 7;
        float4 v = ((const float4*)(g_o + (t0 + row) * 32))[c4];
        float* d = &sX[row * 33 + c4 * 4];
        d[0] = v.x; d[1] = v.y; d[2] = v.z; d[3] = v.w;
    }
    __syncthreads();

    const int tr = tid >> 3, q8 = tid & 7;
    const int c0 = q8 * 4;
    const int gt = t0 + tr;
    u64 accp[2] = {0, 0};

    #pragma unroll 4
    for (int kd = 0; kd < 32; kd++) {
        float a = sX[tr * 33 + kd];
        u64 ap = pack2(a, a);
        ulonglong2 w0 = *(const ulonglong2*)&sWp[kd * 32 + c0];
        accp[0] = ffma2(ap, w0.x, accp[0]);
        accp[1] = ffma2(ap, w0.y, accp[1]);
    }
    float xv[4];
    {
        float4 h0 = *(const float4*)(g_h + gt * 32 + c0);
        float2 u0 = unpack2(accp[0]), u1 = unpack2(accp[1]);
        xv[0] = h0.x + u0.x + sB[c0 + 0];
        xv[1] = h0.y + u0.y + sB[c0 + 1];
        xv[2] = h0.z + u1.x + sB[c0 + 2];
        xv[3] = h0.w + u1.y + sB[c0 + 3];
    }
    float s = 0.f, ss = 0.f;
    #pragma unroll
    for (int i = 0; i < 4; i++) { s += xv[i]; ss += xv[i] * xv[i]; }
    s  += __shfl_xor_sync(0xffffffffu, s, 1);
    ss += __shfl_xor_sync(0xffffffffu, ss, 1);
    s  += __shfl_xor_sync(0xffffffffu, s, 2);
    ss += __shfl_xor_sync(0xffffffffu, ss, 2);
    s  += __shfl_xor_sync(0xffffffffu, s, 4);
    ss += __shfl_xor_sync(0xffffffffu, ss, 4);
    const float mu = s * 0.03125f;
    const float rs = rsqrtf(ss * 0.03125f - mu * mu + 1e-5f);
    float h2r[4];
    #pragma unroll
    for (int i = 0; i < 4; i++)
        h2r[i] = (xv[i] - mu) * rs * sB[64 + c0 + i] + sB[96 + c0 + i];

    __syncthreads();
    #pragma unroll
    for (int i = 0; i < 4; i++) sX[tr * 33 + c0 + i] = h2r[i];
    __syncthreads();

    const int ttb = tid >> 4;
    const int oo  = tid & 15;
    u64 accB[2][4];
    #pragma unroll
    for (int j = 0; j < 2; j++)
        #pragma unroll
        for (int i = 0; i < 4; i++) accB[j][i] = 0;

    #pragma unroll 4
    for (int k = 0; k < 32; k++) {
        float a0 = sX[(ttb * 2 + 0) * 33 + k];
        float a1 = sX[(ttb * 2 + 1) * 33 + k];
        u64 ap0 = pack2(a0, a0), ap1 = pack2(a1, a1);
        const ulonglong2* wr = (const ulonglong2*)&sW1[k * 128 + oo * 8];
        ulonglong2 ww0 = wr[0], ww1 = wr[1];
        u64 wv[4] = {ww0.x, ww0.y, ww1.x, ww1.y};
        #pragma unroll
        for (int i = 0; i < 4; i++) {
            accB[0][i] = ffma2(ap0, wv[i], accB[0][i]);
            accB[1][i] = ffma2(ap1, wv[i], accB[1][i]);
        }
    }
    #pragma unroll
    for (int j = 0; j < 2; j++)
        #pragma unroll
        for (int i = 0; i < 4; i++) {
            float2 u = unpack2(accB[j][i]);
            float* d = &sHid[(ttb * 2 + j) * 129 + oo * 8 + 2 * i];
            d[0] = fmaxf(u.x + sb1[oo * 8 + 2 * i], 0.f);
            d[1] = fmaxf(u.y + sb1[oo * 8 + 2 * i + 1], 0.f);
        }
    __syncthreads();

    u64 accC[2] = {0, 0};
    #pragma unroll 4
    for (int k = 0; k < 128; k++) {
        float a = sHid[tr * 129 + k];
        u64 ap = pack2(a, a);
        ulonglong2 w0 = *(const ulonglong2*)&sW2[k * 32 + c0];
        accC[0] = ffma2(ap, w0.x, accC[0]);
        accC[1] = ffma2(ap, w0.y, accC[1]);
    }
    float2 u0 = unpack2(accC[0]), u1 = unpack2(accC[1]);
    *(float4*)(out + gt * 32 + c0) = make_float4(
        h2r[0] + u0.x + sB[32 + c0 + 0],
        h2r[1] + u0.y + sB[32 + c0 + 1],
        h2r[2] + u1.x + sB[32 + c0 + 2],
        h2r[3] + u1.y + sB[32 + c0 + 3]);
}

// ---------------------------------------------------------------------------
extern "C" void kernel_launch(void* const* d_in, const int* in_sizes, int n_in,
                              void* d_out, int out_size)
{
    const float* x   = (const float*)d_in[0];
    const float* Wq  = (const float*)d_in[1];
    const float* Wk  = (const float*)d_in[2];
    const float* Wv  = (const float*)d_in[3];
    const float* Wp  = (const float*)d_in[4];
    const float* bp  = (const float*)d_in[5];
    const float* g1  = (const float*)d_in[6];
    const float* b1  = (const float*)d_in[7];
    const float* W1  = (const float*)d_in[8];
    const float* b1f = (const float*)d_in[9];
    const float* W2  = (const float*)d_in[10];
    const float* b2f = (const float*)d_in[11];
    const float* g2  = (const float*)d_in[12];
    const float* bt2 = (const float*)d_in[13];
    float* out = (float*)d_out;

    cudaFuncSetAttribute((const void*)k_post,
                         cudaFuncAttributeMaxDynamicSharedMemorySize, SM3_BYTES);

    k_ln_qkv<<<BT_ / 32, 128>>>(x, Wq, Wk, Wv, g1, b1);

    dim3 ga(B_ * 4, 8);
    k_attn<<<ga, 256>>>();

    k_post<<<BT_ / 32, 256, SM3_BYTES>>>(out, Wp, bp, W1, b1f, W2, b2f, g2, bt2);
}

// round 9
// speedup vs baseline: 1.9922x; 1.1152x over previous
#include <cuda_runtime.h>
#include <cuda_fp16.h>

// ---------------------------------------------------------------------------
// DecoderBlock: x:(8,2048,32), H=4, hd=8.
// LN/QKV/post: fp32 f32x2 SIMT. Attention: tensor cores —
// QK^T via mma.m16n8k8.tf32, softmax via ex2.approx.f16x2 (packed MUFU),
// PV via mma.m16n8k16.f16 (fp32 accum); balanced causal pairing;
// double-buffered K/V staging with one bar.sync per tile.
// ---------------------------------------------------------------------------

constexpr int B_  = 8;
constexpr int T_  = 2048;
constexpr int D_  = 32;
constexpr int BT_ = B_ * T_;

__device__ float g_h[BT_ * D_];   // LN1 output
__device__ float g_q[BT_ * D_];   // (B,H,T,8), pre-scaled by log2e/sqrt(8)
__device__ float g_k[BT_ * D_];
__device__ float g_v[BT_ * D_];
__device__ float g_o[BT_ * D_];   // attention out (B*T,32), normalized

typedef unsigned long long u64;
typedef unsigned int u32;

static __device__ __forceinline__ u64 ffma2(u64 a, u64 b, u64 c) {
    u64 d; asm("fma.rn.f32x2 %0, %1, %2, %3;" : "=l"(d) : "l"(a), "l"(b), "l"(c));
    return d;
}
static __device__ __forceinline__ u64 pack2(float x, float y) {
    u64 d; asm("mov.b64 %0, {%1, %2};" : "=l"(d) : "f"(x), "f"(y));
    return d;
}
static __device__ __forceinline__ float2 unpack2(u64 d) {
    float2 r; asm("mov.b64 {%0, %1}, %2;" : "=f"(r.x), "=f"(r.y) : "l"(d));
    return r;
}
static __device__ __forceinline__ u32 cvt_tf32(float f) {
    u32 u; asm("cvt.rna.tf32.f32 %0, %1;" : "=r"(u) : "f"(f));
    return u;
}
static __device__ __forceinline__ u32 h2u(__half2 h) {
    u32 u; __builtin_memcpy(&u, &h, 4); return u;
}
static __device__ __forceinline__ __half2 u2h(u32 u) {
    __half2 h; __builtin_memcpy(&h, &u, 4); return h;
}
// packed half2 exp2
static __device__ __forceinline__ __half2 hex2(__half2 h) {
    u32 u = h2u(h);
    asm("ex2.approx.f16x2 %0, %0;" : "+r"(u));
    return u2h(u);
}
// causal mask half2 for key pair (k, k+1) vs row r: lo half = key k
static __device__ __forceinline__ __half2 mask2(int k, int r) {
    u32 m = (k + 1 <= r) ? 0x3C003C00u : ((k <= r) ? 0x00003C00u : 0u);
    return u2h(m);
}
// S = Q(16x8) * K^T(8x8), tf32, C zero-init.
static __device__ __forceinline__ void mma_tf32_zero(float* d, const u32* a, const u32* b) {
    asm("mma.sync.aligned.m16n8k8.row.col.f32.tf32.tf32.f32 "
        "{%0,%1,%2,%3}, {%4,%5,%6,%7}, {%8,%9}, {%10,%11,%12,%13};"
        : "=f"(d[0]), "=f"(d[1]), "=f"(d[2]), "=f"(d[3])
        : "r"(a[0]), "r"(a[1]), "r"(a[2]), "r"(a[3]),
          "r"(b[0]), "r"(b[1]),
          "f"(0.f), "f"(0.f), "f"(0.f), "f"(0.f));
}
// O += P(16x16,f16) * V(16x8,f16), fp32 accumulate.
static __device__ __forceinline__ void mma_f16(float* d, const u32* a, const u32* b) {
    asm("mma.sync.aligned.m16n8k16.row.col.f32.f16.f16.f32 "
        "{%0,%1,%2,%3}, {%4,%5,%6,%7}, {%8,%9}, {%0,%1,%2,%3};"
        : "+f"(d[0]), "+f"(d[1]), "+f"(d[2]), "+f"(d[3])
        : "r"(a[0]), "r"(a[1]), "r"(a[2]), "r"(a[3]),
          "r"(b[0]), "r"(b[1]));
}

// ---------------------------------------------------------------------------
// Kernel 1: LN1 + QKV. 32 tokens/block, 128 threads, grid 512. (unchanged)
// ---------------------------------------------------------------------------
__global__ __launch_bounds__(128) void k_ln_qkv(
    const float* __restrict__ x,
    const float* __restrict__ Wq, const float* __restrict__ Wk,
    const float* __restrict__ Wv,
    const float* __restrict__ g1, const float* __restrict__ b1)
{
    __shared__ __align__(16) float sh_h[32][33];
    __shared__ __align__(16) float sh_w[32][96];   // [d][qkv*32 + head*8 + kk]

    const int tid = threadIdx.x;
    const int t0  = blockIdx.x * 32;

    for (int i4 = tid; i4 < 768; i4 += 128) {
        int i = i4 * 4;
        int type = i >> 10, rem = i & 1023;
        int head = rem >> 8, d = (rem >> 3) & 31, kk = rem & 7;
        const float* W = (type == 0) ? Wq : (type == 1) ? Wk : Wv;
        *(float4*)&sh_w[d][type * 32 + head * 8 + kk] = *(const float4*)(W + rem);
    }

    const int tk = tid >> 2, part = tid & 3;
    const int t  = t0 + tk;
    const int c0 = part * 8;
    const float4* xr = (const float4*)(x + t * 32 + c0);
    float4 v0 = xr[0], v1 = xr[1];
    float s  = v0.x + v0.y + v0.z + v0.w + v1.x + v1.y + v1.z + v1.w;
    float ss = v0.x*v0.x + v0.y*v0.y + v0.z*v0.z + v0.w*v0.w
             + v1.x*v1.x + v1.y*v1.y + v1.z*v1.z + v1.w*v1.w;
    s  += __shfl_xor_sync(0xffffffffu, s, 1);
    ss += __shfl_xor_sync(0xffffffffu, ss, 1);
    s  += __shfl_xor_sync(0xffffffffu, s, 2);
    ss += __shfl_xor_sync(0xffffffffu, ss, 2);
    const float mu = s * 0.03125f;
    const float rs = rsqrtf(ss * 0.03125f - mu * mu + 1e-5f);
    float hv[8];
    {
        const float* vv = (const float*)&v0;
        #pragma unroll
        for (int i = 0; i < 4; i++)
            hv[i] = (vv[i] - mu) * rs * __ldg(g1 + c0 + i) + __ldg(b1 + c0 + i);
        const float* vw = (const float*)&v1;
        #pragma unroll
        for (int i = 0; i < 4; i++)
            hv[4 + i] = (vw[i] - mu) * rs * __ldg(g1 + c0 + 4 + i) + __ldg(b1 + c0 + 4 + i);
    }
    #pragma unroll
    for (int i = 0; i < 8; i++) sh_h[tk][c0 + i] = hv[i];
    float4* hr = (float4*)(g_h + t * 32 + c0);
    hr[0] = make_float4(hv[0], hv[1], hv[2], hv[3]);
    hr[1] = make_float4(hv[4], hv[5], hv[6], hv[7]);
    __syncthreads();

    const int to = tid >> 3;
    const int oo = tid & 7;
    u64 acc0[6] = {0,0,0,0,0,0}, acc1[6] = {0,0,0,0,0,0};

    #pragma unroll 4
    for (int kd = 0; kd < 32; kd++) {
        float a0 = sh_h[2 * to][kd];
        float a1 = sh_h[2 * to + 1][kd];
        u64 ap0 = pack2(a0, a0), ap1 = pack2(a1, a1);
        const ulonglong2* wr = (const ulonglong2*)&sh_w[kd][oo * 12];
        ulonglong2 w0 = wr[0], w1 = wr[1], w2 = wr[2];
        u64 wv[6] = {w0.x, w0.y, w1.x, w1.y, w2.x, w2.y};
        #pragma unroll
        for (int i = 0; i < 6; i++) {
            acc0[i] = ffma2(ap0, wv[i], acc0[i]);
            acc1[i] = ffma2(ap1, wv[i], acc1[i]);
        }
    }

    const float QS = 0.51006973f;            // log2(e)/sqrt(8)
    const int b   = t0 >> 11;
    const int ttl = (t0 & 2047) + 2 * to;
    #pragma unroll
    for (int i2 = 0; i2 < 6; i2++) {
        int o    = oo * 12 + 2 * i2;
        int type = o >> 5;
        int head = (o >> 3) & 3;
        int kk   = o & 7;
        float* base = (type == 0) ? g_q : (type == 1) ? g_k : g_v;
        float sc = (type == 0) ? QS : 1.f;
        float2 u0 = unpack2(acc0[i2]);
        float2 u1 = unpack2(acc1[i2]);
        float* p = base + ((b * 4 + head) * 2048 + ttl) * 8 + kk;
        *(float2*)(p)     = make_float2(u0.x * sc, u0.y * sc);
        *(float2*)(p + 8) = make_float2(u1.x * sc, u1.y * sc);
    }
}

// ---------------------------------------------------------------------------
// Kernel 2: causal attention with tensor cores, f16x2 softmax, dbl-buffer.
// grid (32, 8), 256 threads (8 warps). Warp w owns query rows [16w,16w+16)
// of tiles j*128 (qa) and (15-j)*128 (qb). Loop key tiles kt=0..15-j.
// ---------------------------------------------------------------------------
static __device__ __forceinline__ void attn_dchunk(
    const u32* __restrict__ qf, const u32 kb[2][2], const u32* __restrict__ vb,
    float* __restrict__ o, float& l0, float& l1,
    bool diag, int keybase, int r0, int tig2)
{
    float s0[4], s1[4];
    mma_tf32_zero(s0, qf, kb[0]);
    mma_tf32_zero(s1, qf, kb[1]);
    __half2 h0 = hex2(__floats2half2_rn(s0[0], s0[1]));   // row r0,   keys kb0
    __half2 h1 = hex2(__floats2half2_rn(s0[2], s0[3]));   // row r0+8, keys kb0
    __half2 h2 = hex2(__floats2half2_rn(s1[0], s1[1]));   // row r0,   keys kb1
    __half2 h3 = hex2(__floats2half2_rn(s1[2], s1[3]));   // row r0+8, keys kb1
    if (diag) {
        const int k0 = keybase + tig2;
        const int k1 = keybase + 8 + tig2;
        h0 = __hmul2(h0, mask2(k0, r0));
        h1 = __hmul2(h1, mask2(k0, r0 + 8));
        h2 = __hmul2(h2, mask2(k1, r0));
        h3 = __hmul2(h3, mask2(k1, r0 + 8));
    }
    {
        float2 f0 = __half22float2(__hadd2(h0, h2));
        l0 += f0.x + f0.y;
        float2 f1 = __half22float2(__hadd2(h1, h3));
        l1 += f1.x + f1.y;
    }
    u32 a[4] = { h2u(h0), h2u(h1), h2u(h2), h2u(h3) };
    mma_f16(o, a, vb);
}

__global__ __launch_bounds__(256) void k_attn()
{
    __shared__ u32 sK[2][128 * 12];   // tf32 K tiles, row stride 12
    __shared__ u32 sV[2][8 * 68];     // half2 V: [dim][keypair], stride 68

    const int tid = threadIdx.x;
    const int w   = tid >> 5;          // warp 0..7
    const int ln  = tid & 31;
    const int g   = ln >> 2;           // groupID 0..7
    const int tig = ln & 3;            // 0..3
    const int bh  = blockIdx.x;
    const int j   = blockIdx.y;        // query tiles j and 15-j
    const int jhi = 15 - j;

    const float* Qg = g_q + bh * T_ * 8;
    const int qa0 = j   * 128 + w * 16 + g;
    const int qb0 = jhi * 128 + w * 16 + g;

    u32 qaf[4], qbf[4];
    qaf[0] = cvt_tf32(Qg[(qa0)     * 8 + tig]);
    qaf[1] = cvt_tf32(Qg[(qa0 + 8) * 8 + tig]);
    qaf[2] = cvt_tf32(Qg[(qa0)     * 8 + tig + 4]);
    qaf[3] = cvt_tf32(Qg[(qa0 + 8) * 8 + tig + 4]);
    qbf[0] = cvt_tf32(Qg[(qb0)     * 8 + tig]);
    qbf[1] = cvt_tf32(Qg[(qb0 + 8) * 8 + tig]);
    qbf[2] = cvt_tf32(Qg[(qb0)     * 8 + tig + 4]);
    qbf[3] = cvt_tf32(Qg[(qb0 + 8) * 8 + tig + 4]);

    float oa[4] = {0.f, 0.f, 0.f, 0.f}, ob[4] = {0.f, 0.f, 0.f, 0.f};
    float la0 = 0.f, la1 = 0.f, lb0 = 0.f, lb1 = 0.f;

    const int srow  = tid >> 1;        // staging row 0..127
    const int shalf = tid & 1;
    const float* Kr = g_k + (bh * T_ + srow) * 8 + shalf * 4;
    const float* Vr = g_v + (bh * T_ + srow) * 8 + shalf * 4;

    // prefetch tile 0
    float4 kreg = *(const float4*)(Kr);
    float4 vreg = *(const float4*)(Vr);

    for (int kt = 0; kt <= jhi; kt++) {
        const int s0 = kt * 128;
        const int buf = kt & 1;

        // ---- write staged registers into smem[buf] ----
        {
            u32* kd = &sK[buf][srow * 12 + shalf * 4];
            kd[0] = cvt_tf32(kreg.x); kd[1] = cvt_tf32(kreg.y);
            kd[2] = cvt_tf32(kreg.z); kd[3] = cvt_tf32(kreg.w);
            float px = __shfl_xor_sync(0xffffffffu, vreg.x, 2);
            float py = __shfl_xor_sync(0xffffffffu, vreg.y, 2);
            float pz = __shfl_xor_sync(0xffffffffu, vreg.z, 2);
            float pw = __shfl_xor_sync(0xffffffffu, vreg.w, 2);
            if ((tid & 2) == 0) {            // even row of the key pair
                int kp = tid >> 2;
                int d0 = shalf * 4;
                sV[buf][(d0 + 0) * 68 + kp] = h2u(__floats2half2_rn(vreg.x, px));
                sV[buf][(d0 + 1) * 68 + kp] = h2u(__floats2half2_rn(vreg.y, py));
                sV[buf][(d0 + 2) * 68 + kp] = h2u(__floats2half2_rn(vreg.z, pz));
                sV[buf][(d0 + 3) * 68 + kp] = h2u(__floats2half2_rn(vreg.w, pw));
            }
        }
        __syncthreads();

        // ---- prefetch next tile (overlaps with compute below) ----
        if (kt < jhi) {
            kreg = *(const float4*)(Kr + (kt + 1) * 128 * 8);
            vreg = *(const float4*)(Vr + (kt + 1) * 128 * 8);
        }

        const bool qaAct = (kt <= j);
        const bool dA = (kt == j), dB = (kt == jhi);

        #pragma unroll 2
        for (int c = 0; c < 8; c++) {
            u32 kb[2][2];
            const u32* k0r = &sK[buf][(16 * c + g) * 12];
            const u32* k1r = &sK[buf][(16 * c + 8 + g) * 12];
            kb[0][0] = k0r[tig]; kb[0][1] = k0r[tig + 4];
            kb[1][0] = k1r[tig]; kb[1][1] = k1r[tig + 4];
            u32 vb[2];
            vb[0] = sV[buf][g * 68 + 8 * c + tig];
            vb[1] = sV[buf][g * 68 + 8 * c + tig + 4];

            if (qaAct)
                attn_dchunk(qaf, kb, vb, oa, la0, la1, dA, s0 + 16 * c, qa0, 2 * tig);
            attn_dchunk(qbf, kb, vb, ob, lb0, lb1, dB, s0 + 16 * c, qb0, 2 * tig);
        }
        // single sync per tile: next iteration writes smem[buf^1], whose
        // readers finished before this iteration's sync.
    }

    // ---- finalize: reduce l over the quad, normalize, store ----
    la0 += __shfl_xor_sync(0xffffffffu, la0, 1);
    la0 += __shfl_xor_sync(0xffffffffu, la0, 2);
    la1 += __shfl_xor_sync(0xffffffffu, la1, 1);
    la1 += __shfl_xor_sync(0xffffffffu, la1, 2);
    lb0 += __shfl_xor_sync(0xffffffffu, lb0, 1);
    lb0 += __shfl_xor_sync(0xffffffffu, lb0, 2);
    lb1 += __shfl_xor_sync(0xffffffffu, lb1, 1);
    lb1 += __shfl_xor_sync(0xffffffffu, lb1, 2);
    const float ra0 = __fdividef(1.f, la0);
    const float ra1 = __fdividef(1.f, la1);
    const float rb0 = __fdividef(1.f, lb0);
    const float rb1 = __fdividef(1.f, lb1);

    const int bb = bh >> 2, h = bh & 3;
    const int colo = h * 8 + 2 * tig;
    *(float2*)(g_o + (bb * T_ + qa0)     * 32 + colo) = make_float2(oa[0] * ra0, oa[1] * ra0);
    *(float2*)(g_o + (bb * T_ + qa0 + 8) * 32 + colo) = make_float2(oa[2] * ra1, oa[3] * ra1);
    *(float2*)(g_o + (bb * T_ + qb0)     * 32 + colo) = make_float2(ob[0] * rb0, ob[1] * rb0);
    *(float2*)(g_o + (bb * T_ + qb0 + 8) * 32 + colo) = make_float2(ob[2] * rb1, ob[3] * rb1);
}

// ---------------------------------------------------------------------------
// Kernel 3: proj + residual + LN2 + FFN + residual. 32 tokens, 256 threads,
// grid 512. (unchanged)
// ---------------------------------------------------------------------------
constexpr int SM3_FLOATS = 1024 + 4096 + 4096 + 128 + 128 + 32 * 33 + 32 * 129;
constexpr int SM3_BYTES  = SM3_FLOATS * 4;

__global__ __launch_bounds__(256) void k_post(
    float* __restrict__ out,
    const float* __restrict__ Wp, const float* __restrict__ bp,
    const float* __restrict__ W1, const float* __restrict__ b1v,
    const float* __restrict__ W2, const float* __restrict__ b2v,
    const float* __restrict__ g2, const float* __restrict__ bt2)
{
    extern __shared__ float sm[];
    float* sWp  = sm;
    float* sW1  = sWp + 1024;
    float* sW2  = sW1 + 4096;
    float* sB   = sW2 + 4096;
    float* sb1  = sB + 128;
    float* sX   = sb1 + 128;
    float* sHid = sX + 32 * 33;

    const int tid = threadIdx.x;
    const int t0  = blockIdx.x * 32;

    *(float4*)&sWp[tid * 4] = *(const float4*)(Wp + tid * 4);
    for (int i4 = tid; i4 < 1024; i4 += 256)
        *(float4*)&sW1[i4 * 4] = *(const float4*)(W1 + i4 * 4);
    for (int i4 = tid; i4 < 1024; i4 += 256)
        *(float4*)&sW2[i4 * 4] = *(const float4*)(W2 + i4 * 4);
    if (tid < 32) { sB[tid] = bp[tid]; sB[32 + tid] = b2v[tid];
                    sB[64 + tid] = g2[tid]; sB[96 + tid] = bt2[tid]; }
    if (tid >= 128 && tid < 256) sb1[tid - 128] = b1v[tid - 128];

    {
        int row = tid >> 3, c4 = tid & 7;
        float4 v = ((const float4*)(g_o + (t0 + row) * 32))[c4];
        float* d = &sX[row * 33 + c4 * 4];
        d[0] = v.x; d[1] = v.y; d[2] = v.z; d[3] = v.w;
    }
    __syncthreads();

    const int tr = tid >> 3, q8 = tid & 7;
    const int c0 = q8 * 4;
    const int gt = t0 + tr;
    u64 accp[2] = {0, 0};

    #pragma unroll 4
    for (int kd = 0; kd < 32; kd++) {
        float a = sX[tr * 33 + kd];
        u64 ap = pack2(a, a);
        ulonglong2 w0 = *(const ulonglong2*)&sWp[kd * 32 + c0];
        accp[0] = ffma2(ap, w0.x, accp[0]);
        accp[1] = ffma2(ap, w0.y, accp[1]);
    }
    float xv[4];
    {
        float4 h0 = *(const float4*)(g_h + gt * 32 + c0);
        float2 u0 = unpack2(accp[0]), u1 = unpack2(accp[1]);
        xv[0] = h0.x + u0.x + sB[c0 + 0];
        xv[1] = h0.y + u0.y + sB[c0 + 1];
        xv[2] = h0.z + u1.x + sB[c0 + 2];
        xv[3] = h0.w + u1.y + sB[c0 + 3];
    }
    float s = 0.f, ss = 0.f;
    #pragma unroll
    for (int i = 0; i < 4; i++) { s += xv[i]; ss += xv[i] * xv[i]; }
    s  += __shfl_xor_sync(0xffffffffu, s, 1);
    ss += __shfl_xor_sync(0xffffffffu, ss, 1);
    s  += __shfl_xor_sync(0xffffffffu, s, 2);
    ss += __shfl_xor_sync(0xffffffffu, ss, 2);
    s  += __shfl_xor_sync(0xffffffffu, s, 4);
    ss += __shfl_xor_sync(0xffffffffu, ss, 4);
    const float mu = s * 0.03125f;
    const float rs = rsqrtf(ss * 0.03125f - mu * mu + 1e-5f);
    float h2r[4];
    #pragma unroll
    for (int i = 0; i < 4; i++)
        h2r[i] = (xv[i] - mu) * rs * sB[64 + c0 + i] + sB[96 + c0 + i];

    __syncthreads();
    #pragma unroll
    for (int i = 0; i < 4; i++) sX[tr * 33 + c0 + i] = h2r[i];
    __syncthreads();

    const int ttb = tid >> 4;
    const int oo  = tid & 15;
    u64 accB[2][4];
    #pragma unroll
    for (int j = 0; j < 2; j++)
        #pragma unroll
        for (int i = 0; i < 4; i++) accB[j][i] = 0;

    #pragma unroll 4
    for (int k = 0; k < 32; k++) {
        float a0 = sX[(ttb * 2 + 0) * 33 + k];
        float a1 = sX[(ttb * 2 + 1) * 33 + k];
        u64 ap0 = pack2(a0, a0), ap1 = pack2(a1, a1);
        const ulonglong2* wr = (const ulonglong2*)&sW1[k * 128 + oo * 8];
        ulonglong2 ww0 = wr[0], ww1 = wr[1];
        u64 wv[4] = {ww0.x, ww0.y, ww1.x, ww1.y};
        #pragma unroll
        for (int i = 0; i < 4; i++) {
            accB[0][i] = ffma2(ap0, wv[i], accB[0][i]);
            accB[1][i] = ffma2(ap1, wv[i], accB[1][i]);
        }
    }
    #pragma unroll
    for (int j = 0; j < 2; j++)
        #pragma unroll
        for (int i = 0; i < 4; i++) {
            float2 u = unpack2(accB[j][i]);
            float* d = &sHid[(ttb * 2 + j) * 129 + oo * 8 + 2 * i];
            d[0] = fmaxf(u.x + sb1[oo * 8 + 2 * i], 0.f);
            d[1] = fmaxf(u.y + sb1[oo * 8 + 2 * i + 1], 0.f);
        }
    __syncthreads();

    u64 accC[2] = {0, 0};
    #pragma unroll 4
    for (int k = 0; k < 128; k++) {
        float a = sHid[tr * 129 + k];
        u64 ap = pack2(a, a);
        ulonglong2 w0 = *(const ulonglong2*)&sW2[k * 32 + c0];
        accC[0] = ffma2(ap, w0.x, accC[0]);
        accC[1] = ffma2(ap, w0.y, accC[1]);
    }
    float2 u0 = unpack2(accC[0]), u1 = unpack2(accC[1]);
    *(float4*)(out + gt * 32 + c0) = make_float4(
        h2r[0] + u0.x + sB[32 + c0 + 0],
        h2r[1] + u0.y + sB[32 + c0 + 1],
        h2r[2] + u1.x + sB[32 + c0 + 2],
        h2r[3] + u1.y + sB[32 + c0 + 3]);
}

// ---------------------------------------------------------------------------
extern "C" void kernel_launch(void* const* d_in, const int* in_sizes, int n_in,
                              void* d_out, int out_size)
{
    const float* x   = (const float*)d_in[0];
    const float* Wq  = (const float*)d_in[1];
    const float* Wk  = (const float*)d_in[2];
    const float* Wv  = (const float*)d_in[3];
    const float* Wp  = (const float*)d_in[4];
    const float* bp  = (const float*)d_in[5];
    const float* g1  = (const float*)d_in[6];
    const float* b1  = (const float*)d_in[7];
    const float* W1  = (const float*)d_in[8];
    const float* b1f = (const float*)d_in[9];
    const float* W2  = (const float*)d_in[10];
    const float* b2f = (const float*)d_in[11];
    const float* g2  = (const float*)d_in[12];
    const float* bt2 = (const float*)d_in[13];
    float* out = (float*)d_out;

    cudaFuncSetAttribute((const void*)k_post,
                         cudaFuncAttributeMaxDynamicSharedMemorySize, SM3_BYTES);

    k_ln_qkv<<<BT_ / 32, 128>>>(x, Wq, Wk, Wv, g1, b1);

    dim3 ga(B_ * 4, 8);
    k_attn<<<ga, 256>>>();

    k_post<<<BT_ / 32, 256, SM3_BYTES>>>(out, Wp, bp, W1, b1f, W2, b2f, g2, bt2);
}